// round 6
// baseline (speedup 1.0000x reference)
#include <cuda_runtime.h>
#include <cuda_bf16.h>

// Problem constants (fixed by the dataset)
#define NN   100000      // nodes
#define NE   1000000     // edges
#define DIM  128
#define NR   16

#define TILE_E 128       // edges per GEMM tile
#define NTILE_E ((NE + TILE_E - 1) / TILE_E)     // 7813
#define NTILE_N ((NN + TILE_E - 1) / TILE_E)     // 782
#define SMEM_BYTES (2 * 128 * 128 * 4)           // As + Ws = 131072

// ---------------- scratch (static device globals; no allocation) -----------
__device__ float g_X  [(size_t)NN * DIM];   // layer-1 input features
__device__ float g_H  [(size_t)NN * DIM];   // layer-1 output / layer-2 input
__device__ float g_AGG[(size_t)NN * DIM];   // per-layer scatter accumulator
__device__ int   g_perm[NE];                // edge ids sorted by relation
__device__ int   g_cnt[NN];
__device__ float g_inv[NN];
__device__ int   g_binOff[NR + 1];
__device__ int   g_binCur[NR];
__device__ int   g_hist[NR];

// ---------------- small utility kernels ------------------------------------
__global__ void k_init_counts() {
    int i = blockIdx.x * blockDim.x + threadIdx.x;
    if (i < NN) g_cnt[i] = 0;
    if (i < NR) g_hist[i] = 0;
}

// x[node] = emb[entity[node]] ; one float4 per thread
__global__ void k_gather(const float* __restrict__ emb, const int* __restrict__ ent) {
    int i = blockIdx.x * blockDim.x + threadIdx.x;   // over NN*32 float4s
    if (i >= NN * 32) return;
    int node = i >> 5, c = i & 31;
    reinterpret_cast<float4*>(g_X)[(size_t)node * 32 + c] =
        reinterpret_cast<const float4*>(emb)[(size_t)ent[node] * 32 + c];
}

__global__ void k_histo(const int* __restrict__ dstA, const int* __restrict__ rel) {
    __shared__ int sh[NR];
    if (threadIdx.x < NR) sh[threadIdx.x] = 0;
    __syncthreads();
    for (int e = blockIdx.x * blockDim.x + threadIdx.x; e < NE; e += gridDim.x * blockDim.x) {
        atomicAdd(&g_cnt[dstA[e]], 1);
        atomicAdd(&sh[rel[e]], 1);
    }
    __syncthreads();
    if (threadIdx.x < NR) atomicAdd(&g_hist[threadIdx.x], sh[threadIdx.x]);
}

__global__ void k_scan() {
    int acc = 0;
    for (int r = 0; r < NR; r++) {
        g_binOff[r] = acc; g_binCur[r] = acc; acc += g_hist[r];
    }
    g_binOff[NR] = acc;
}

__global__ void k_perm(const int* __restrict__ rel) {
    for (int e = blockIdx.x * blockDim.x + threadIdx.x; e < NE; e += gridDim.x * blockDim.x) {
        int pos = atomicAdd(&g_binCur[rel[e]], 1);
        g_perm[pos] = e;
    }
}

__global__ void k_inv() {
    int i = blockIdx.x * blockDim.x + threadIdx.x;
    if (i < NN) {
        int c = g_cnt[i];
        g_inv[i] = 1.0f / (float)(c > 0 ? c : 1);
    }
}

__global__ void k_zero_agg() {
    int i = blockIdx.x * blockDim.x + threadIdx.x;   // over NN*32 float4s
    if (i < NN * 32) reinterpret_cast<float4*>(g_AGG)[i] = make_float4(0.f, 0.f, 0.f, 0.f);
}

// ---------------- edge GEMM: msgs = X[src] @ W[rel], scatter-add to AGG[dst]
// Block: 256 threads, 128 edges x 128 outs x K=128, 8x8 register tile/thread.
__global__ void __launch_bounds__(256, 1)
k_edge_gemm(const float* __restrict__ W,
            const int* __restrict__ srcA, const int* __restrict__ dstA,
            const int* __restrict__ rel, int useH) {
    extern __shared__ float sm[];
    float* As = sm;              // [k][e]  128x128
    float* Ws = sm + 128 * 128;  // [k][o]  128x128
    __shared__ int sSrc[TILE_E], sDst[TILE_E], sRel[TILE_E];
    __shared__ int sRunS[TILE_E + 1], sRunR[TILE_E];
    __shared__ int sNRuns;

    const float* __restrict__ Xin = useH ? g_H : g_X;
    int tid = threadIdx.x;
    int base = blockIdx.x * TILE_E;
    int nE = NE - base; if (nE > TILE_E) nE = TILE_E;

    for (int i = tid; i < TILE_E; i += 256) {
        if (i < nE) {
            int p = g_perm[base + i];
            sSrc[i] = srcA[p]; sDst[i] = dstA[p]; sRel[i] = rel[p];
        } else { sSrc[i] = -1; sDst[i] = 0; sRel[i] = -1; }
    }
    __syncthreads();

    // gather A transposed: As[k][e]
    for (int idx = tid; idx < TILE_E * 32; idx += 256) {
        int e = idx >> 5, c = idx & 31;
        float4 v = make_float4(0.f, 0.f, 0.f, 0.f);
        int s = sSrc[e];
        if (s >= 0) v = reinterpret_cast<const float4*>(Xin)[(size_t)s * 32 + c];
        int k0 = c * 4;
        As[(k0 + 0) * 128 + e] = v.x;
        As[(k0 + 1) * 128 + e] = v.y;
        As[(k0 + 2) * 128 + e] = v.z;
        As[(k0 + 3) * 128 + e] = v.w;
    }
    if (tid == 0) {  // contiguous relation runs (perm is relation-sorted)
        int n = 0, i = 0;
        while (i < nE) {
            int r = sRel[i];
            sRunS[n] = i; sRunR[n] = r;
            while (i < nE && sRel[i] == r) i++;
            n++;
        }
        sRunS[n] = nE; sNRuns = n;
    }
    __syncthreads();

    int nRuns = sNRuns;
    int row = tid >> 4, col = tid & 15;   // 16x16 thread grid

    for (int run = 0; run < nRuns; ++run) {
        int rs = sRunS[run], re = sRunS[run + 1], r = sRunR[run];
        // stage W_r (64KB) into smem; layout [d][o] matches [k][o] directly
        const float4* Wg = reinterpret_cast<const float4*>(W + (size_t)r * DIM * DIM);
        for (int i = tid; i < 4096; i += 256) reinterpret_cast<float4*>(Ws)[i] = Wg[i];
        __syncthreads();

        float acc[8][8];
        #pragma unroll
        for (int i = 0; i < 8; i++)
            #pragma unroll
            for (int j = 0; j < 8; j++) acc[i][j] = 0.f;

        #pragma unroll 4
        for (int k = 0; k < 128; k++) {
            float4 a0 = *reinterpret_cast<float4*>(&As[k * 128 + row * 8]);
            float4 a1 = *reinterpret_cast<float4*>(&As[k * 128 + row * 8 + 4]);
            float4 b0 = *reinterpret_cast<float4*>(&Ws[k * 128 + col * 8]);
            float4 b1 = *reinterpret_cast<float4*>(&Ws[k * 128 + col * 8 + 4]);
            float a[8] = {a0.x, a0.y, a0.z, a0.w, a1.x, a1.y, a1.z, a1.w};
            float b[8] = {b0.x, b0.y, b0.z, b0.w, b1.x, b1.y, b1.z, b1.w};
            #pragma unroll
            for (int i = 0; i < 8; i++)
                #pragma unroll
                for (int j = 0; j < 8; j++)
                    acc[i][j] = fmaf(a[i], b[j], acc[i][j]);
        }

        // scatter rows belonging to this run
        #pragma unroll
        for (int i = 0; i < 8; i++) {
            int e = row * 8 + i;
            if (e >= rs && e < re) {
                float* outp = &g_AGG[(size_t)sDst[e] * DIM + col * 8];
                #pragma unroll
                for (int j = 0; j < 8; j++) atomicAdd(outp + j, acc[i][j]);
            }
        }
        __syncthreads();   // protect Ws before next run reload
    }
}

// ---------------- root GEMM + epilogue: out = [relu](AGG*inv + Xin @ Wroot)
__global__ void __launch_bounds__(256, 1)
k_root(const float* __restrict__ Wroot, int useH, int doRelu, float* __restrict__ outExt) {
    extern __shared__ float sm[];
    float* As = sm;              // [k][n]
    float* Ws = sm + 128 * 128;  // [k][o]

    const float* __restrict__ Xin = useH ? g_H : g_X;
    float* __restrict__ outp = doRelu ? g_H : outExt;

    int tid = threadIdx.x;
    int base = blockIdx.x * TILE_E;
    int nRow = NN - base; if (nRow > TILE_E) nRow = TILE_E;

    for (int idx = tid; idx < TILE_E * 32; idx += 256) {
        int e = idx >> 5, c = idx & 31;
        float4 v = make_float4(0.f, 0.f, 0.f, 0.f);
        if (e < nRow) v = reinterpret_cast<const float4*>(Xin)[(size_t)(base + e) * 32 + c];
        int k0 = c * 4;
        As[(k0 + 0) * 128 + e] = v.x;
        As[(k0 + 1) * 128 + e] = v.y;
        As[(k0 + 2) * 128 + e] = v.z;
        As[(k0 + 3) * 128 + e] = v.w;
    }
    {
        const float4* Wg = reinterpret_cast<const float4*>(Wroot);
        for (int i = tid; i < 4096; i += 256) reinterpret_cast<float4*>(Ws)[i] = Wg[i];
    }
    __syncthreads();

    int row = tid >> 4, col = tid & 15;
    float acc[8][8];
    #pragma unroll
    for (int i = 0; i < 8; i++)
        #pragma unroll
        for (int j = 0; j < 8; j++) acc[i][j] = 0.f;

    #pragma unroll 4
    for (int k = 0; k < 128; k++) {
        float4 a0 = *reinterpret_cast<float4*>(&As[k * 128 + row * 8]);
        float4 a1 = *reinterpret_cast<float4*>(&As[k * 128 + row * 8 + 4]);
        float4 b0 = *reinterpret_cast<float4*>(&Ws[k * 128 + col * 8]);
        float4 b1 = *reinterpret_cast<float4*>(&Ws[k * 128 + col * 8 + 4]);
        float a[8] = {a0.x, a0.y, a0.z, a0.w, a1.x, a1.y, a1.z, a1.w};
        float b[8] = {b0.x, b0.y, b0.z, b0.w, b1.x, b1.y, b1.z, b1.w};
        #pragma unroll
        for (int i = 0; i < 8; i++)
            #pragma unroll
            for (int j = 0; j < 8; j++)
                acc[i][j] = fmaf(a[i], b[j], acc[i][j]);
    }

    #pragma unroll
    for (int i = 0; i < 8; i++) {
        int n = base + row * 8 + i;
        if (n < NN) {
            float inv = g_inv[n];
            const float4* ag = reinterpret_cast<const float4*>(&g_AGG[(size_t)n * DIM + col * 8]);
            float4 g0 = ag[0], g1 = ag[1];
            float v[8];
            v[0] = acc[i][0] + g0.x * inv; v[1] = acc[i][1] + g0.y * inv;
            v[2] = acc[i][2] + g0.z * inv; v[3] = acc[i][3] + g0.w * inv;
            v[4] = acc[i][4] + g1.x * inv; v[5] = acc[i][5] + g1.y * inv;
            v[6] = acc[i][6] + g1.z * inv; v[7] = acc[i][7] + g1.w * inv;
            if (doRelu) {
                #pragma unroll
                for (int j = 0; j < 8; j++) v[j] = fmaxf(v[j], 0.f);
            }
            float4* op = reinterpret_cast<float4*>(&outp[(size_t)n * DIM + col * 8]);
            op[0] = make_float4(v[0], v[1], v[2], v[3]);
            op[1] = make_float4(v[4], v[5], v[6], v[7]);
        }
    }
}

// ---------------- launch ----------------------------------------------------
extern "C" void kernel_launch(void* const* d_in, const int* in_sizes, int n_in,
                              void* d_out, int out_size) {
    const int*   entity = (const int*)  d_in[0];
    const int*   eidx   = (const int*)  d_in[1];   // [2, NE]
    const int*   etype  = (const int*)  d_in[2];
    /* d_in[3] edge_norm: unused by the reference math */
    const float* emb    = (const float*)d_in[4];
    const float* W1     = (const float*)d_in[5];
    const float* root1  = (const float*)d_in[6];
    const float* W2     = (const float*)d_in[7];
    const float* root2  = (const float*)d_in[8];
    float* out = (float*)d_out;

    const int* srcA = eidx;
    const int* dstA = eidx + NE;

    cudaFuncSetAttribute((const void*)k_edge_gemm,
                         cudaFuncAttributeMaxDynamicSharedMemorySize, SMEM_BYTES);
    cudaFuncSetAttribute((const void*)k_root,
                         cudaFuncAttributeMaxDynamicSharedMemorySize, SMEM_BYTES);

    // setup
    k_init_counts<<<(NN + 255) / 256, 256>>>();
    k_gather<<<(NN * 32 + 255) / 256, 256>>>(emb, entity);
    k_histo<<<592, 256>>>(dstA, etype);
    k_scan<<<1, 1>>>();
    k_perm<<<592, 256>>>(etype);
    k_inv<<<(NN + 255) / 256, 256>>>();

    // layer 1
    k_zero_agg<<<(NN * 32 + 255) / 256, 256>>>();
    k_edge_gemm<<<NTILE_E, 256, SMEM_BYTES>>>(W1, srcA, dstA, etype, 0);
    k_root<<<NTILE_N, 256, SMEM_BYTES>>>(root1, 0, 1, out);

    // layer 2
    k_zero_agg<<<(NN * 32 + 255) / 256, 256>>>();
    k_edge_gemm<<<NTILE_E, 256, SMEM_BYTES>>>(W2, srcA, dstA, etype, 1);
    k_root<<<NTILE_N, 256, SMEM_BYTES>>>(root2, 1, 0, out);
}

// round 8
// speedup vs baseline: 1.2619x; 1.2619x over previous
#include <cuda_runtime.h>
#include <cuda_bf16.h>

// Problem constants (fixed by the dataset)
#define NN   100000      // nodes
#define NE   1000000     // edges
#define DIM  128
#define NR   16

#define TILE_E 128       // edges per GEMM tile
#define NTILE_E ((NE + TILE_E - 1) / TILE_E)     // 7813
#define NTILE_N ((NN + TILE_E - 1) / TILE_E)     // 782
#define SMEM_BYTES (2 * 128 * 128 * 4)           // As + Ws = 131072

#define PERM_BLOCK 1024
#define PERM_GRID ((NE + PERM_BLOCK - 1) / PERM_BLOCK)

typedef unsigned long long u64;

// ---------------- scratch (static device globals; no allocation) -----------
__device__ float g_X  [(size_t)NN * DIM];   // layer-1 input features
__device__ float g_H  [(size_t)NN * DIM];   // layer-1 output / layer-2 input
__device__ float g_AGG[(size_t)NN * DIM];   // per-layer scatter accumulator
__device__ int   g_perm[NE];                // edge ids sorted by relation
__device__ int   g_cnt[NN];
__device__ float g_inv[NN];
__device__ int   g_binOff[NR + 1];
__device__ int   g_binCur[NR];
__device__ int   g_hist[NR];

// ---------------- packed fp32x2 helpers (Blackwell 2x fp32 path) ------------
__device__ __forceinline__ u64 dup_f32(float x) {
    u64 r;
    asm("mov.b64 %0, {%1, %1};" : "=l"(r) : "f"(x));
    return r;
}
__device__ __forceinline__ void ffma2(u64& d, u64 a, u64 b) {
    asm("fma.rn.f32x2 %0, %1, %2, %0;" : "+l"(d) : "l"(a), "l"(b));
}
__device__ __forceinline__ float2 unpk(u64 v) {
    float2 f;
    asm("mov.b64 {%0, %1}, %2;" : "=f"(f.x), "=f"(f.y) : "l"(v));
    return f;
}
__device__ __forceinline__ void red_add_v4(float* p, float a, float b, float c, float d) {
    asm volatile("red.global.add.v4.f32 [%0], {%1, %2, %3, %4};"
                 :: "l"(p), "f"(a), "f"(b), "f"(c), "f"(d) : "memory");
}

// ---------------- small utility kernels ------------------------------------
__global__ void k_init_counts() {
    int i = blockIdx.x * blockDim.x + threadIdx.x;
    if (i < NN) g_cnt[i] = 0;
    if (i < NR) g_hist[i] = 0;
}

// x[node] = emb[entity[node]] ; one float4 per thread
__global__ void k_gather(const float* __restrict__ emb, const int* __restrict__ ent) {
    int i = blockIdx.x * blockDim.x + threadIdx.x;   // over NN*32 float4s
    if (i >= NN * 32) return;
    int node = i >> 5, c = i & 31;
    reinterpret_cast<float4*>(g_X)[(size_t)node * 32 + c] =
        reinterpret_cast<const float4*>(emb)[(size_t)ent[node] * 32 + c];
}

__global__ void k_histo(const int* __restrict__ dstA, const int* __restrict__ rel) {
    __shared__ int sh[NR];
    if (threadIdx.x < NR) sh[threadIdx.x] = 0;
    __syncthreads();
    for (int e = blockIdx.x * blockDim.x + threadIdx.x; e < NE; e += gridDim.x * blockDim.x) {
        atomicAdd(&g_cnt[dstA[e]], 1);
        atomicAdd(&sh[rel[e]], 1);
    }
    __syncthreads();
    if (threadIdx.x < NR) atomicAdd(&g_hist[threadIdx.x], sh[threadIdx.x]);
}

__global__ void k_scan() {
    int acc = 0;
    for (int r = 0; r < NR; r++) {
        g_binOff[r] = acc; g_binCur[r] = acc; acc += g_hist[r];
    }
    g_binOff[NR] = acc;
}

// Block-aggregated relation sort: smem histogram, ONE global atomic per
// relation per block, then local scatter. (Replaces 1M contended global
// atomics on 16 counters.)
__global__ void k_perm(const int* __restrict__ rel) {
    __shared__ int lc[NR], lb[NR];
    int base = blockIdx.x * PERM_BLOCK;
    int n = NE - base; if (n > PERM_BLOCK) n = PERM_BLOCK;
    if (threadIdx.x < NR) lc[threadIdx.x] = 0;
    __syncthreads();
    int myRel[PERM_BLOCK / 256], myRank[PERM_BLOCK / 256];
    #pragma unroll
    for (int t = 0; t < PERM_BLOCK / 256; t++) {
        int i = threadIdx.x + t * 256;
        if (i < n) {
            int r = rel[base + i];
            myRel[t] = r;
            myRank[t] = atomicAdd(&lc[r], 1);
        } else myRel[t] = -1;
    }
    __syncthreads();
    if (threadIdx.x < NR)
        lb[threadIdx.x] = atomicAdd(&g_binCur[threadIdx.x], lc[threadIdx.x]);
    __syncthreads();
    #pragma unroll
    for (int t = 0; t < PERM_BLOCK / 256; t++)
        if (myRel[t] >= 0)
            g_perm[lb[myRel[t]] + myRank[t]] = base + threadIdx.x + t * 256;
}

__global__ void k_inv() {
    int i = blockIdx.x * blockDim.x + threadIdx.x;
    if (i < NN) {
        int c = g_cnt[i];
        g_inv[i] = 1.0f / (float)(c > 0 ? c : 1);
    }
}

__global__ void k_zero_agg() {
    int i = blockIdx.x * blockDim.x + threadIdx.x;   // over NN*32 float4s
    if (i < NN * 32) reinterpret_cast<float4*>(g_AGG)[i] = make_float4(0.f, 0.f, 0.f, 0.f);
}

// ---------------- edge GEMM: msgs = X[src] @ W[rel], scatter-add to AGG[dst]
// Block: 256 threads, 128 edges x 128 outs x K=128, 8x8 register tile/thread,
// packed fp32x2 accumulate (4 x u64 accumulators per output row-slice).
__global__ void __launch_bounds__(256, 1)
k_edge_gemm(const float* __restrict__ W,
            const int* __restrict__ srcA, const int* __restrict__ dstA,
            const int* __restrict__ rel, int useH) {
    extern __shared__ float sm[];
    float* As = sm;              // [k][e]  128x128
    float* Ws = sm + 128 * 128;  // [k][o]  128x128
    __shared__ int sSrc[TILE_E], sDst[TILE_E], sRel[TILE_E];
    __shared__ int sRunS[TILE_E + 1], sRunR[TILE_E];
    __shared__ int sNRuns;

    const float* __restrict__ Xin = useH ? g_H : g_X;
    int tid = threadIdx.x;
    int base = blockIdx.x * TILE_E;
    int nE = NE - base; if (nE > TILE_E) nE = TILE_E;

    for (int i = tid; i < TILE_E; i += 256) {
        if (i < nE) {
            int p = g_perm[base + i];
            sSrc[i] = srcA[p]; sDst[i] = dstA[p]; sRel[i] = rel[p];
        } else { sSrc[i] = -1; sDst[i] = 0; sRel[i] = -1; }
    }
    __syncthreads();

    // gather A transposed: As[k][e]
    for (int idx = tid; idx < TILE_E * 32; idx += 256) {
        int e = idx >> 5, c = idx & 31;
        float4 v = make_float4(0.f, 0.f, 0.f, 0.f);
        int s = sSrc[e];
        if (s >= 0) v = reinterpret_cast<const float4*>(Xin)[(size_t)s * 32 + c];
        int k0 = c * 4;
        As[(k0 + 0) * 128 + e] = v.x;
        As[(k0 + 1) * 128 + e] = v.y;
        As[(k0 + 2) * 128 + e] = v.z;
        As[(k0 + 3) * 128 + e] = v.w;
    }
    if (tid == 0) {  // contiguous relation runs (perm is relation-sorted)
        int n = 0, i = 0;
        while (i < nE) {
            int r = sRel[i];
            sRunS[n] = i; sRunR[n] = r;
            while (i < nE && sRel[i] == r) i++;
            n++;
        }
        sRunS[n] = nE; sNRuns = n;
    }
    __syncthreads();

    int nRuns = sNRuns;
    int row = tid >> 4, col = tid & 15;   // 16x16 thread grid

    for (int run = 0; run < nRuns; ++run) {
        int rs = sRunS[run], re = sRunS[run + 1], r = sRunR[run];
        // stage W_r (64KB) into smem; layout [d][o] matches [k][o] directly
        const float4* Wg = reinterpret_cast<const float4*>(W + (size_t)r * DIM * DIM);
        for (int i = tid; i < 4096; i += 256) reinterpret_cast<float4*>(Ws)[i] = Wg[i];
        __syncthreads();

        u64 acc[8][4];
        #pragma unroll
        for (int i = 0; i < 8; i++)
            #pragma unroll
            for (int j = 0; j < 4; j++) acc[i][j] = 0ull;

        #pragma unroll 4
        for (int k = 0; k < 128; k++) {
            float4 a0 = *reinterpret_cast<float4*>(&As[k * 128 + row * 8]);
            float4 a1 = *reinterpret_cast<float4*>(&As[k * 128 + row * 8 + 4]);
            ulonglong2 b0 = *reinterpret_cast<ulonglong2*>(&Ws[k * 128 + col * 8]);
            ulonglong2 b1 = *reinterpret_cast<ulonglong2*>(&Ws[k * 128 + col * 8 + 4]);
            u64 bp[4] = {b0.x, b0.y, b1.x, b1.y};
            float a[8] = {a0.x, a0.y, a0.z, a0.w, a1.x, a1.y, a1.z, a1.w};
            #pragma unroll
            for (int i = 0; i < 8; i++) {
                u64 ad = dup_f32(a[i]);
                #pragma unroll
                for (int j = 0; j < 4; j++) ffma2(acc[i][j], ad, bp[j]);
            }
        }

        // scatter rows belonging to this run (vectorized global reduction)
        #pragma unroll
        for (int i = 0; i < 8; i++) {
            int e = row * 8 + i;
            if (e >= rs && e < re) {
                float* outp = &g_AGG[(size_t)sDst[e] * DIM + col * 8];
                float2 f0 = unpk(acc[i][0]), f1 = unpk(acc[i][1]);
                float2 f2 = unpk(acc[i][2]), f3 = unpk(acc[i][3]);
                red_add_v4(outp,     f0.x, f0.y, f1.x, f1.y);
                red_add_v4(outp + 4, f2.x, f2.y, f3.x, f3.y);
            }
        }
        __syncthreads();   // protect Ws before next run reload
    }
}

// ---------------- root GEMM + epilogue: out = [relu](AGG*inv + Xin @ Wroot)
__global__ void __launch_bounds__(256, 1)
k_root(const float* __restrict__ Wroot, int useH, int doRelu, float* __restrict__ outExt) {
    extern __shared__ float sm[];
    float* As = sm;              // [k][n]
    float* Ws = sm + 128 * 128;  // [k][o]

    const float* __restrict__ Xin = useH ? g_H : g_X;
    float* __restrict__ outp = doRelu ? g_H : outExt;

    int tid = threadIdx.x;
    int base = blockIdx.x * TILE_E;
    int nRow = NN - base; if (nRow > TILE_E) nRow = TILE_E;

    for (int idx = tid; idx < TILE_E * 32; idx += 256) {
        int e = idx >> 5, c = idx & 31;
        float4 v = make_float4(0.f, 0.f, 0.f, 0.f);
        if (e < nRow) v = reinterpret_cast<const float4*>(Xin)[(size_t)(base + e) * 32 + c];
        int k0 = c * 4;
        As[(k0 + 0) * 128 + e] = v.x;
        As[(k0 + 1) * 128 + e] = v.y;
        As[(k0 + 2) * 128 + e] = v.z;
        As[(k0 + 3) * 128 + e] = v.w;
    }
    {
        const float4* Wg = reinterpret_cast<const float4*>(Wroot);
        for (int i = tid; i < 4096; i += 256) reinterpret_cast<float4*>(Ws)[i] = Wg[i];
    }
    __syncthreads();

    int row = tid >> 4, col = tid & 15;
    u64 acc[8][4];
    #pragma unroll
    for (int i = 0; i < 8; i++)
        #pragma unroll
        for (int j = 0; j < 4; j++) acc[i][j] = 0ull;

    #pragma unroll 4
    for (int k = 0; k < 128; k++) {
        float4 a0 = *reinterpret_cast<float4*>(&As[k * 128 + row * 8]);
        float4 a1 = *reinterpret_cast<float4*>(&As[k * 128 + row * 8 + 4]);
        ulonglong2 b0 = *reinterpret_cast<ulonglong2*>(&Ws[k * 128 + col * 8]);
        ulonglong2 b1 = *reinterpret_cast<ulonglong2*>(&Ws[k * 128 + col * 8 + 4]);
        u64 bp[4] = {b0.x, b0.y, b1.x, b1.y};
        float a[8] = {a0.x, a0.y, a0.z, a0.w, a1.x, a1.y, a1.z, a1.w};
        #pragma unroll
        for (int i = 0; i < 8; i++) {
            u64 ad = dup_f32(a[i]);
            #pragma unroll
            for (int j = 0; j < 4; j++) ffma2(acc[i][j], ad, bp[j]);
        }
    }

    #pragma unroll
    for (int i = 0; i < 8; i++) {
        int n = base + row * 8 + i;
        if (n < NN) {
            float inv = g_inv[n];
            const float4* ag = reinterpret_cast<const float4*>(&g_AGG[(size_t)n * DIM + col * 8]);
            float4 g0 = ag[0], g1 = ag[1];
            float2 f0 = unpk(acc[i][0]), f1 = unpk(acc[i][1]);
            float2 f2 = unpk(acc[i][2]), f3 = unpk(acc[i][3]);
            float v[8];
            v[0] = f0.x + g0.x * inv; v[1] = f0.y + g0.y * inv;
            v[2] = f1.x + g0.z * inv; v[3] = f1.y + g0.w * inv;
            v[4] = f2.x + g1.x * inv; v[5] = f2.y + g1.y * inv;
            v[6] = f3.x + g1.z * inv; v[7] = f3.y + g1.w * inv;
            if (doRelu) {
                #pragma unroll
                for (int j = 0; j < 8; j++) v[j] = fmaxf(v[j], 0.f);
            }
            float4* op = reinterpret_cast<float4*>(&outp[(size_t)n * DIM + col * 8]);
            op[0] = make_float4(v[0], v[1], v[2], v[3]);
            op[1] = make_float4(v[4], v[5], v[6], v[7]);
        }
    }
}

// ---------------- launch ----------------------------------------------------
extern "C" void kernel_launch(void* const* d_in, const int* in_sizes, int n_in,
                              void* d_out, int out_size) {
    const int*   entity = (const int*)  d_in[0];
    const int*   eidx   = (const int*)  d_in[1];   // [2, NE]
    const int*   etype  = (const int*)  d_in[2];
    /* d_in[3] edge_norm: unused by the reference math */
    const float* emb    = (const float*)d_in[4];
    const float* W1     = (const float*)d_in[5];
    const float* root1  = (const float*)d_in[6];
    const float* W2     = (const float*)d_in[7];
    const float* root2  = (const float*)d_in[8];
    float* out = (float*)d_out;

    const int* srcA = eidx;
    const int* dstA = eidx + NE;

    cudaFuncSetAttribute((const void*)k_edge_gemm,
                         cudaFuncAttributeMaxDynamicSharedMemorySize, SMEM_BYTES);
    cudaFuncSetAttribute((const void*)k_root,
                         cudaFuncAttributeMaxDynamicSharedMemorySize, SMEM_BYTES);

    // setup
    k_init_counts<<<(NN + 255) / 256, 256>>>();
    k_gather<<<(NN * 32 + 255) / 256, 256>>>(emb, entity);
    k_histo<<<592, 256>>>(dstA, etype);
    k_scan<<<1, 1>>>();
    k_perm<<<PERM_GRID, 256>>>(etype);
    k_inv<<<(NN + 255) / 256, 256>>>();

    // layer 1
    k_zero_agg<<<(NN * 32 + 255) / 256, 256>>>();
    k_edge_gemm<<<NTILE_E, 256, SMEM_BYTES>>>(W1, srcA, dstA, etype, 0);
    k_root<<<NTILE_N, 256, SMEM_BYTES>>>(root1, 0, 1, out);

    // layer 2
    k_zero_agg<<<(NN * 32 + 255) / 256, 256>>>();
    k_edge_gemm<<<NTILE_E, 256, SMEM_BYTES>>>(W2, srcA, dstA, etype, 1);
    k_root<<<NTILE_N, 256, SMEM_BYTES>>>(root2, 1, 0, out);
}

// round 17
// speedup vs baseline: 1.8789x; 1.4889x over previous
#include <cuda_runtime.h>
#include <cuda_bf16.h>

// Problem constants (fixed by the dataset)
#define NN   100000      // nodes
#define NE   1000000     // edges
#define DIM  128
#define NR   16

#define TILE_E 128
#define NTILE_E ((NE + TILE_E - 1) / TILE_E)     // 7813
#define NTILE_N ((NN + TILE_E - 1) / TILE_E)     // 782
#define SMEM_BYTES (2 * 128 * 128 * 4)           // scalar kernels: As + Ws

// bf16 tile images: 128 rows x 136 (padded) bf16 -> conflict-free fragment LDS
#define BSTRIDE 136
#define IMG_USH (128 * BSTRIDE)                  // 17408 ushorts = 34816 bytes
#define MMA_SMEM (4 * IMG_USH * 2)               // Ahi,Alo,Bhi,Blo = 139264

#define PERM_BLOCK 1024
#define PERM_GRID ((NE + PERM_BLOCK - 1) / PERM_BLOCK)   // 977
#define WSPLIT_N (2 * NR * DIM * DIM)            // 524288

typedef unsigned long long u64;
typedef unsigned int u32;

// ---------------- scratch (static device globals; no allocation) -----------
__device__ float g_X  [(size_t)NN * DIM];
__device__ float g_H  [(size_t)NN * DIM];
__device__ float g_AGG[(size_t)NN * DIM];
__device__ int   g_perm[NE];
__device__ int   g_cnt[NN];
__device__ float g_inv[NN];
__device__ int   g_binOff[NR + 1];
__device__ int   g_binCur[NR];
__device__ int   g_hist[NR];
__device__ int   g_done;
__device__ int   g_tileRel[NTILE_E];             // relation if single-run tile, else -1
__device__ __align__(16) unsigned short g_Bhi[2 * NR * IMG_USH];  // W^T hi images
__device__ __align__(16) unsigned short g_Blo[2 * NR * IMG_USH];  // W^T lo images

// ---------------- helpers ---------------------------------------------------
__device__ __forceinline__ u64 dup_f32(float x) {
    u64 r; asm("mov.b64 %0, {%1, %1};" : "=l"(r) : "f"(x)); return r;
}
__device__ __forceinline__ void ffma2(u64& d, u64 a, u64 b) {
    asm("fma.rn.f32x2 %0, %1, %2, %0;" : "+l"(d) : "l"(a), "l"(b));
}
__device__ __forceinline__ float2 unpk(u64 v) {
    float2 f; asm("mov.b64 {%0, %1}, %2;" : "=f"(f.x), "=f"(f.y) : "l"(v)); return f;
}
__device__ __forceinline__ void red_add_v4(float* p, float a, float b, float c, float d) {
    asm volatile("red.global.add.v4.f32 [%0], {%1, %2, %3, %4};"
                 :: "l"(p), "f"(a), "f"(b), "f"(c), "f"(d) : "memory");
}
__device__ __forceinline__ unsigned short bf16_us(float x) {
    return __bfloat16_as_ushort(__float2bfloat16(x));
}
__device__ __forceinline__ void mma16816(float* c, const u32* a, u32 b0, u32 b1) {
    asm volatile(
        "mma.sync.aligned.m16n8k16.row.col.f32.bf16.bf16.f32 "
        "{%0,%1,%2,%3}, {%4,%5,%6,%7}, {%8,%9}, {%0,%1,%2,%3};"
        : "+f"(c[0]), "+f"(c[1]), "+f"(c[2]), "+f"(c[3])
        : "r"(a[0]), "r"(a[1]), "r"(a[2]), "r"(a[3]), "r"(b0), "r"(b1));
}

// ---------------- launch #1: init + gather X + W split + zero AGG ----------
__global__ void k_setup(const float* __restrict__ emb, const int* __restrict__ ent,
                        const float* __restrict__ W1, const float* __restrict__ W2) {
    int i = blockIdx.x * blockDim.x + threadIdx.x;
    if (i == 0) g_done = 0;
    if (i < NN) g_cnt[i] = 0;
    if (i < NR) g_hist[i] = 0;
    if (i < WSPLIT_N) {
        int l = i >> 18;
        int rem = i & 262143;
        int r = rem >> 14;
        int e = rem & 16383;               // d*128 + o
        int d = e >> 7, o = e & 127;
        const float* Wp = l ? W2 : W1;
        float v = Wp[(size_t)r * 16384 + e];
        unsigned short hu = bf16_us(v);
        float hv = __bfloat162float(__ushort_as_bfloat16(hu));
        unsigned short lu = bf16_us(v - hv);
        size_t base = (size_t)(l * NR + r) * IMG_USH;
        g_Bhi[base + o * BSTRIDE + d] = hu;   // B image: row n=o, col k=d
        g_Blo[base + o * BSTRIDE + d] = lu;
    }
    if (i < NN * 32) {
        reinterpret_cast<float4*>(g_AGG)[i] = make_float4(0.f, 0.f, 0.f, 0.f);
        int node = i >> 5, c = i & 31;
        reinterpret_cast<float4*>(g_X)[(size_t)node * 32 + c] =
            reinterpret_cast<const float4*>(emb)[(size_t)ent[node] * 32 + c];
    }
}

// ---------------- launch #2: histogram + last-block scan --------------------
__global__ void k_histo(const int* __restrict__ dstA, const int* __restrict__ rel) {
    __shared__ int sh[NR];
    __shared__ int sLast;
    if (threadIdx.x < NR) sh[threadIdx.x] = 0;
    __syncthreads();
    for (int e = blockIdx.x * blockDim.x + threadIdx.x; e < NE; e += gridDim.x * blockDim.x) {
        atomicAdd(&g_cnt[dstA[e]], 1);
        atomicAdd(&sh[rel[e]], 1);
    }
    __syncthreads();
    if (threadIdx.x < NR) atomicAdd(&g_hist[threadIdx.x], sh[threadIdx.x]);
    __threadfence();
    if (threadIdx.x == 0) sLast = (atomicAdd(&g_done, 1) == (int)gridDim.x - 1);
    __syncthreads();
    if (sLast && threadIdx.x == 0) {
        int acc = 0;
        for (int r = 0; r < NR; r++) {
            int h = atomicAdd(&g_hist[r], 0);   // L2-coherent read (skip stale L1)
            g_binOff[r] = acc; g_binCur[r] = acc; acc += h;
        }
        g_binOff[NR] = acc;
        g_done = 0;   // reset for next replay (determinism)
    }
}

// ---------------- launch #3: block-aggregated sort + inv + tileRel ----------
__global__ void k_perm(const int* __restrict__ rel) {
    __shared__ int lc[NR], lb[NR];
    int gid = blockIdx.x * blockDim.x + threadIdx.x;
    if (gid < NN) {
        int c = g_cnt[gid];
        g_inv[gid] = 1.0f / (float)(c > 0 ? c : 1);
    }
    if (gid < NTILE_E) {
        int lo = gid * TILE_E, hi = lo + TILE_E; if (hi > NE) hi = NE;
        int res = -1;
        #pragma unroll
        for (int r = 0; r < NR; r++)
            if (g_binOff[r] <= lo && hi <= g_binOff[r + 1]) res = r;
        g_tileRel[gid] = res;
    }
    int base = blockIdx.x * PERM_BLOCK;
    int n = NE - base; if (n > PERM_BLOCK) n = PERM_BLOCK;
    if (threadIdx.x < NR) lc[threadIdx.x] = 0;
    __syncthreads();
    int myRel[PERM_BLOCK / 256], myRank[PERM_BLOCK / 256];
    #pragma unroll
    for (int t = 0; t < PERM_BLOCK / 256; t++) {
        int i = threadIdx.x + t * 256;
        if (i < n) { int r = rel[base + i]; myRel[t] = r; myRank[t] = atomicAdd(&lc[r], 1); }
        else myRel[t] = -1;
    }
    __syncthreads();
    if (threadIdx.x < NR) lb[threadIdx.x] = atomicAdd(&g_binCur[threadIdx.x], lc[threadIdx.x]);
    __syncthreads();
    #pragma unroll
    for (int t = 0; t < PERM_BLOCK / 256; t++)
        if (myRel[t] >= 0) g_perm[lb[myRel[t]] + myRank[t]] = base + threadIdx.x + t * 256;
}

__global__ void k_zero_agg() {
    int i = blockIdx.x * blockDim.x + threadIdx.x;
    if (i < NN * 32) reinterpret_cast<float4*>(g_AGG)[i] = make_float4(0.f, 0.f, 0.f, 0.f);
}

// ---------------- tensor edge GEMM (single-relation tiles), mma.sync --------
// 256 thr = 8 warps (4 m-tiles x 2 n-halves). D[128e x 128o] = A @ W^T via
// 3-pass bf16-split m16n8k16 HMMA. Results staged to smem, scattered red.v4.
__global__ void __launch_bounds__(256, 1)
k_edge_mma(const int* __restrict__ srcA, const int* __restrict__ dstA, int layer) {
    int t = blockIdx.x;
    int r = g_tileRel[t];
    if (r < 0) return;

    extern __shared__ unsigned short smu[];
    unsigned short* Ahi = smu;
    unsigned short* Alo = smu + IMG_USH;
    unsigned short* Bhi = smu + 2 * IMG_USH;
    unsigned short* Blo = smu + 3 * IMG_USH;
    __shared__ int sDst[TILE_E], sSrc[TILE_E];

    const float* __restrict__ Xin = layer ? g_H : g_X;
    int tid = threadIdx.x, wid = tid >> 5, lid = tid & 31;
    int base = t * TILE_E;
    int nE = NE - base; if (nE > TILE_E) nE = TILE_E;

    for (int i = tid; i < TILE_E; i += 256) {
        if (i < nE) { int p = g_perm[base + i]; sSrc[i] = srcA[p]; sDst[i] = dstA[p]; }
        else { sSrc[i] = -1; sDst[i] = 0; }
    }
    // stage B: flat 16B copies of pre-split images
    {
        const float4* bh = reinterpret_cast<const float4*>(g_Bhi + (size_t)(layer * NR + r) * IMG_USH);
        const float4* bl = reinterpret_cast<const float4*>(g_Blo + (size_t)(layer * NR + r) * IMG_USH);
        for (int i = tid; i < IMG_USH / 8; i += 256) {
            reinterpret_cast<float4*>(Bhi)[i] = bh[i];
            reinterpret_cast<float4*>(Blo)[i] = bl[i];
        }
    }
    __syncthreads();
    // stage A: gather fp32 rows, split hi/lo bf16, store padded row-major
    for (int idx = tid; idx < TILE_E * 32; idx += 256) {
        int e = idx >> 5, c = idx & 31, k0 = c * 4;
        float4 v = make_float4(0.f, 0.f, 0.f, 0.f);
        int s = sSrc[e];
        if (s >= 0) v = reinterpret_cast<const float4*>(Xin)[(size_t)s * 32 + c];
        unsigned short hx = bf16_us(v.x), hy = bf16_us(v.y), hz = bf16_us(v.z), hw = bf16_us(v.w);
        unsigned short lx = bf16_us(v.x - __bfloat162float(__ushort_as_bfloat16(hx)));
        unsigned short ly = bf16_us(v.y - __bfloat162float(__ushort_as_bfloat16(hy)));
        unsigned short lz = bf16_us(v.z - __bfloat162float(__ushort_as_bfloat16(hz)));
        unsigned short lw = bf16_us(v.w - __bfloat162float(__ushort_as_bfloat16(hw)));
        u32* ah = reinterpret_cast<u32*>(Ahi);
        u32* al = reinterpret_cast<u32*>(Alo);
        int o = e * (BSTRIDE / 2) + (k0 >> 1);
        ah[o]     = (u32)hx | ((u32)hy << 16);
        ah[o + 1] = (u32)hz | ((u32)hw << 16);
        al[o]     = (u32)lx | ((u32)ly << 16);
        al[o + 1] = (u32)lz | ((u32)lw << 16);
    }
    __syncthreads();

    int g = lid >> 2, tg = lid & 3;
    int m0 = (wid & 3) * 32, n0 = (wid >> 2) * 64;

    float acc[2][8][4];
    #pragma unroll
    for (int i = 0; i < 2; i++)
        #pragma unroll
        for (int j = 0; j < 8; j++)
            #pragma unroll
            for (int q = 0; q < 4; q++) acc[i][j][q] = 0.f;

    const unsigned short* Ap[3] = {Ahi, Ahi, Alo};
    const unsigned short* Bp[3] = {Bhi, Blo, Bhi};
    #pragma unroll
    for (int p = 0; p < 3; p++) {
        const u32* Ab = reinterpret_cast<const u32*>(Ap[p]);
        const u32* Bb = reinterpret_cast<const u32*>(Bp[p]);
        #pragma unroll
        for (int ks = 0; ks < 8; ks++) {
            int kc = ks * 8 + tg;             // u32 col: k0/2 + tg
            u32 a[2][4];
            #pragma unroll
            for (int tt = 0; tt < 2; tt++) {
                int r1 = m0 + tt * 16 + g;
                a[tt][0] = Ab[r1 * 68 + kc];
                a[tt][1] = Ab[(r1 + 8) * 68 + kc];
                a[tt][2] = Ab[r1 * 68 + kc + 4];
                a[tt][3] = Ab[(r1 + 8) * 68 + kc + 4];
            }
            #pragma unroll
            for (int j = 0; j < 8; j++) {
                int n = n0 + j * 8 + g;
                u32 b0 = Bb[n * 68 + kc];
                u32 b1 = Bb[n * 68 + kc + 4];
                mma16816(acc[0][j], a[0], b0, b1);
                mma16816(acc[1][j], a[1], b0, b1);
            }
        }
    }

    // stage accumulators to smem (aliases Ahi/Alo; [128][132] f32)
    __syncthreads();
    float* stg = reinterpret_cast<float*>(Ahi);
    #pragma unroll
    for (int tt = 0; tt < 2; tt++)
        #pragma unroll
        for (int j = 0; j < 8; j++) {
            int r1 = m0 + tt * 16 + g, c = n0 + j * 8 + 2 * tg;
            *reinterpret_cast<float2*>(&stg[r1 * 132 + c]) =
                make_float2(acc[tt][j][0], acc[tt][j][1]);
            *reinterpret_cast<float2*>(&stg[(r1 + 8) * 132 + c]) =
                make_float2(acc[tt][j][2], acc[tt][j][3]);
        }
    __syncthreads();

    // scatter: each thread owns half a row (64 cols) -> 16 red.v4
    int row = tid >> 1, ch = (tid & 1) << 6;
    if (row < nE) {
        float* aggp = &g_AGG[(size_t)sDst[row] * DIM + ch];
        const float* sp = &stg[row * 132 + ch];
        #pragma unroll
        for (int m = 0; m < 16; m++)
            red_add_v4(aggp + m * 4, sp[m * 4], sp[m * 4 + 1], sp[m * 4 + 2], sp[m * 4 + 3]);
    }
}

// ---------------- scalar fallback edge GEMM (boundary tiles only) -----------
__global__ void __launch_bounds__(256, 1)
k_edge_gemm(const float* __restrict__ W,
            const int* __restrict__ srcA, const int* __restrict__ dstA,
            const int* __restrict__ rel, int useH) {
    if (g_tileRel[blockIdx.x] >= 0) return;   // handled by tensor kernel
    extern __shared__ float sm[];
    float* As = sm;
    float* Ws = sm + 128 * 128;
    __shared__ int sSrc[TILE_E], sDst[TILE_E], sRel[TILE_E];
    __shared__ int sRunS[TILE_E + 1], sRunR[TILE_E];
    __shared__ int sNRuns;

    const float* __restrict__ Xin = useH ? g_H : g_X;
    int tid = threadIdx.x;
    int base = blockIdx.x * TILE_E;
    int nE = NE - base; if (nE > TILE_E) nE = TILE_E;

    for (int i = tid; i < TILE_E; i += 256) {
        if (i < nE) {
            int p = g_perm[base + i];
            sSrc[i] = srcA[p]; sDst[i] = dstA[p]; sRel[i] = rel[p];
        } else { sSrc[i] = -1; sDst[i] = 0; sRel[i] = -1; }
    }
    __syncthreads();

    for (int idx = tid; idx < TILE_E * 32; idx += 256) {
        int e = idx >> 5, c = idx & 31;
        float4 v = make_float4(0.f, 0.f, 0.f, 0.f);
        int s = sSrc[e];
        if (s >= 0) v = reinterpret_cast<const float4*>(Xin)[(size_t)s * 32 + c];
        int k0 = c * 4;
        As[(k0 + 0) * 128 + e] = v.x;
        As[(k0 + 1) * 128 + e] = v.y;
        As[(k0 + 2) * 128 + e] = v.z;
        As[(k0 + 3) * 128 + e] = v.w;
    }
    if (tid == 0) {
        int n = 0, i = 0;
        while (i < nE) {
            int r = sRel[i];
            sRunS[n] = i; sRunR[n] = r;
            while (i < nE && sRel[i] == r) i++;
            n++;
        }
        sRunS[n] = nE; sNRuns = n;
    }
    __syncthreads();

    int nRuns = sNRuns;
    int row = tid >> 4, col = tid & 15;

    for (int run = 0; run < nRuns; ++run) {
        int rs = sRunS[run], re = sRunS[run + 1], r = sRunR[run];
        const float4* Wg = reinterpret_cast<const float4*>(W + (size_t)r * DIM * DIM);
        for (int i = tid; i < 4096; i += 256) reinterpret_cast<float4*>(Ws)[i] = Wg[i];
        __syncthreads();

        u64 acc[8][4];
        #pragma unroll
        for (int i = 0; i < 8; i++)
            #pragma unroll
            for (int j = 0; j < 4; j++) acc[i][j] = 0ull;

        #pragma unroll 4
        for (int k = 0; k < 128; k++) {
            float4 a0 = *reinterpret_cast<float4*>(&As[k * 128 + row * 8]);
            float4 a1 = *reinterpret_cast<float4*>(&As[k * 128 + row * 8 + 4]);
            ulonglong2 b0 = *reinterpret_cast<ulonglong2*>(&Ws[k * 128 + col * 8]);
            ulonglong2 b1 = *reinterpret_cast<ulonglong2*>(&Ws[k * 128 + col * 8 + 4]);
            u64 bp[4] = {b0.x, b0.y, b1.x, b1.y};
            float a[8] = {a0.x, a0.y, a0.z, a0.w, a1.x, a1.y, a1.z, a1.w};
            #pragma unroll
            for (int i = 0; i < 8; i++) {
                u64 ad = dup_f32(a[i]);
                #pragma unroll
                for (int j = 0; j < 4; j++) ffma2(acc[i][j], ad, bp[j]);
            }
        }

        #pragma unroll
        for (int i = 0; i < 8; i++) {
            int e = row * 8 + i;
            if (e >= rs && e < re) {
                float* outp = &g_AGG[(size_t)sDst[e] * DIM + col * 8];
                float2 f0 = unpk(acc[i][0]), f1 = unpk(acc[i][1]);
                float2 f2 = unpk(acc[i][2]), f3 = unpk(acc[i][3]);
                red_add_v4(outp,     f0.x, f0.y, f1.x, f1.y);
                red_add_v4(outp + 4, f2.x, f2.y, f3.x, f3.y);
            }
        }
        __syncthreads();
    }
}

// ---------------- root GEMM + epilogue --------------------------------------
__global__ void __launch_bounds__(256, 1)
k_root(const float* __restrict__ Wroot, int useH, int doRelu, float* __restrict__ outExt) {
    extern __shared__ float sm[];
    float* As = sm;
    float* Ws = sm + 128 * 128;

    const float* __restrict__ Xin = useH ? g_H : g_X;
    float* __restrict__ outp = doRelu ? g_H : outExt;

    int tid = threadIdx.x;
    int base = blockIdx.x * TILE_E;
    int nRow = NN - base; if (nRow > TILE_E) nRow = TILE_E;

    for (int idx = tid; idx < TILE_E * 32; idx += 256) {
        int e = idx >> 5, c = idx & 31;
        float4 v = make_float4(0.f, 0.f, 0.f, 0.f);
        if (e < nRow) v = reinterpret_cast<const float4*>(Xin)[(size_t)(base + e) * 32 + c];
        int k0 = c * 4;
        As[(k0 + 0) * 128 + e] = v.x;
        As[(k0 + 1) * 128 + e] = v.y;
        As[(k0 + 2) * 128 + e] = v.z;
        As[(k0 + 3) * 128 + e] = v.w;
    }
    {
        const float4* Wg = reinterpret_cast<const float4*>(Wroot);
        for (int i = tid; i < 4096; i += 256) reinterpret_cast<float4*>(Ws)[i] = Wg[i];
    }
    __syncthreads();

    int row = tid >> 4, col = tid & 15;
    u64 acc[8][4];
    #pragma unroll
    for (int i = 0; i < 8; i++)
        #pragma unroll
        for (int j = 0; j < 4; j++) acc[i][j] = 0ull;

    #pragma unroll 4
    for (int k = 0; k < 128; k++) {
        float4 a0 = *reinterpret_cast<float4*>(&As[k * 128 + row * 8]);
        float4 a1 = *reinterpret_cast<float4*>(&As[k * 128 + row * 8 + 4]);
        ulonglong2 b0 = *reinterpret_cast<ulonglong2*>(&Ws[k * 128 + col * 8]);
        ulonglong2 b1 = *reinterpret_cast<ulonglong2*>(&Ws[k * 128 + col * 8 + 4]);
        u64 bp[4] = {b0.x, b0.y, b1.x, b1.y};
        float a[8] = {a0.x, a0.y, a0.z, a0.w, a1.x, a1.y, a1.z, a1.w};
        #pragma unroll
        for (int i = 0; i < 8; i++) {
            u64 ad = dup_f32(a[i]);
            #pragma unroll
            for (int j = 0; j < 4; j++) ffma2(acc[i][j], ad, bp[j]);
        }
    }

    #pragma unroll
    for (int i = 0; i < 8; i++) {
        int n = base + row * 8 + i;
        if (n < NN) {
            float inv = g_inv[n];
            const float4* ag = reinterpret_cast<const float4*>(&g_AGG[(size_t)n * DIM + col * 8]);
            float4 g0 = ag[0], g1 = ag[1];
            float2 f0 = unpk(acc[i][0]), f1 = unpk(acc[i][1]);
            float2 f2 = unpk(acc[i][2]), f3 = unpk(acc[i][3]);
            float v[8];
            v[0] = f0.x + g0.x * inv; v[1] = f0.y + g0.y * inv;
            v[2] = f1.x + g0.z * inv; v[3] = f1.y + g0.w * inv;
            v[4] = f2.x + g1.x * inv; v[5] = f2.y + g1.y * inv;
            v[6] = f3.x + g1.z * inv; v[7] = f3.y + g1.w * inv;
            if (doRelu) {
                #pragma unroll
                for (int j = 0; j < 8; j++) v[j] = fmaxf(v[j], 0.f);
            }
            float4* op = reinterpret_cast<float4*>(&outp[(size_t)n * DIM + col * 8]);
            op[0] = make_float4(v[0], v[1], v[2], v[3]);
            op[1] = make_float4(v[4], v[5], v[6], v[7]);
        }
    }
}

// ---------------- launch ----------------------------------------------------
extern "C" void kernel_launch(void* const* d_in, const int* in_sizes, int n_in,
                              void* d_out, int out_size) {
    const int*   entity = (const int*)  d_in[0];
    const int*   eidx   = (const int*)  d_in[1];
    const int*   etype  = (const int*)  d_in[2];
    const float* emb    = (const float*)d_in[4];
    const float* W1     = (const float*)d_in[5];
    const float* root1  = (const float*)d_in[6];
    const float* W2     = (const float*)d_in[7];
    const float* root2  = (const float*)d_in[8];
    float* out = (float*)d_out;

    const int* srcA = eidx;
    const int* dstA = eidx + NE;

    cudaFuncSetAttribute((const void*)k_edge_gemm,
                         cudaFuncAttributeMaxDynamicSharedMemorySize, SMEM_BYTES);
    cudaFuncSetAttribute((const void*)k_root,
                         cudaFuncAttributeMaxDynamicSharedMemorySize, SMEM_BYTES);
    cudaFuncSetAttribute((const void*)k_edge_mma,
                         cudaFuncAttributeMaxDynamicSharedMemorySize, MMA_SMEM);

    // setup: 3 launches so k_edge_mma is launch #4 (= the ncu capture slot)
    k_setup<<<(NN * 32 + 255) / 256, 256>>>(emb, entity, W1, W2);
    k_histo<<<592, 256>>>(dstA, etype);
    k_perm<<<PERM_GRID, 256>>>(etype);

    // layer 1
    k_edge_mma<<<NTILE_E, 256, MMA_SMEM>>>(srcA, dstA, 0);          // launch #4
    k_edge_gemm<<<NTILE_E, 256, SMEM_BYTES>>>(W1, srcA, dstA, etype, 0);
    k_root<<<NTILE_N, 256, SMEM_BYTES>>>(root1, 0, 1, out);

    // layer 2
    k_zero_agg<<<(NN * 32 + 255) / 256, 256>>>();
    k_edge_mma<<<NTILE_E, 256, MMA_SMEM>>>(srcA, dstA, 1);
    k_edge_gemm<<<NTILE_E, 256, SMEM_BYTES>>>(W2, srcA, dstA, etype, 1);
    k_root<<<NTILE_N, 256, SMEM_BYTES>>>(root2, 1, 0, out);
}